// round 1
// baseline (speedup 1.0000x reference)
#include <cuda_runtime.h>
#include <math.h>

// instant-NGP HashGrid + 2-layer MLP, fully fused. One thread per point.
//
// Config (hard-coded in the reference):
//   L=16 levels, F=2 feats/level, T=2^19 entries/level, base_res=16,
//   scale=1.447269237440378  ->  res_l = floor(16 * scale^l + 1e-6)
//   dense indexing iff (res+1)^3 <= T  (true for levels 0..4)
//   hash = x*1 ^ y*2654435761 ^ z*805459861, masked by T-1
//   MLP: h = relu(enc @ w1^T) [64], out = sigmoid(h @ w2^T) [1]

#define NPTS (64 * 64 * 64)
#define NLEV 16
#define TSIZE (1u << 19)
#define TMASK (TSIZE - 1u)

// res_l = floor(2^(4 + 8l/15) + 1e-6), verified in double precision.
__device__ __constant__ int kResConst[NLEV] = {
    16, 23, 33, 48, 70, 101, 147, 212, 307, 445, 645, 933, 1351, 1955, 2830, 4096};

// compile-time copy for the unrolled loop (constant folding)
struct LevelCfg { int res; bool dense; };
__device__ __forceinline__ LevelCfg level_cfg(int l) {
    const int R[NLEV] = {16, 23, 33, 48, 70, 101, 147, 212, 307, 445, 645, 933, 1351, 1955, 2830, 4096};
    LevelCfg c; c.res = R[l]; c.dense = (l < 5); return c;
}

__global__ void __launch_bounds__(256, 4)
ngp_fused_kernel(const float* __restrict__ pts,
                 const float2* __restrict__ table,   // [L * T] float2
                 const float* __restrict__ w1,       // [64, 32]
                 const float* __restrict__ w2,       // [64]
                 float* __restrict__ out)            // [NPTS]
{
    __shared__ float s_w1[64 * 32];
    __shared__ float s_w2[64];

    const int tid = threadIdx.x;
    for (int i = tid; i < 64 * 32; i += 256) s_w1[i] = w1[i];
    if (tid < 64) s_w2[tid] = w2[tid];
    __syncthreads();

    const int i = blockIdx.x * 256 + tid;
    if (i >= NPTS) return;

    const float px = pts[3 * i + 0];
    const float py = pts[3 * i + 1];
    const float pz = pts[3 * i + 2];

    float enc[32];

#pragma unroll
    for (int l = 0; l < NLEV; ++l) {
        const LevelCfg cfg = level_cfg(l);
        const float res = (float)cfg.res;

        const float x = px * res, y = py * res, z = pz * res;
        const float fx0 = floorf(x), fy0 = floorf(y), fz0 = floorf(z);
        const float fx = x - fx0, fy = y - fy0, fz = z - fz0;
        const unsigned cx = (unsigned)fx0;
        const unsigned cy = (unsigned)fy0;
        const unsigned cz = (unsigned)fz0;

        const float2* __restrict__ tab = table + (size_t)l * TSIZE;

        // precompute per-dim index contributions for both corner offsets
        unsigned ix[2], iy[2], iz[2];
        if (cfg.dense) {
            const unsigned r1 = (unsigned)(cfg.res + 1);
            ix[0] = cx;            ix[1] = cx + 1u;
            iy[0] = r1 * cy;       iy[1] = r1 * (cy + 1u);
            iz[0] = r1 * r1 * cz;  iz[1] = r1 * r1 * (cz + 1u);
        } else {
            ix[0] = cx;                     ix[1] = cx + 1u;
            iy[0] = cy * 2654435761u;       iy[1] = (cy + 1u) * 2654435761u;
            iz[0] = cz * 805459861u;        iz[1] = (cz + 1u) * 805459861u;
        }

        const float wx[2] = {1.0f - fx, fx};
        const float wy[2] = {1.0f - fy, fy};
        const float wz[2] = {1.0f - fz, fz};

        float e0 = 0.0f, e1 = 0.0f;
#pragma unroll
        for (int c = 0; c < 8; ++c) {
            const int ox = (c >> 2) & 1, oy = (c >> 1) & 1, oz = c & 1;
            unsigned idx;
            if (cfg.dense) idx = (ix[ox] + iy[oy] + iz[oz]) & TMASK;
            else           idx = (ix[ox] ^ iy[oy] ^ iz[oz]) & TMASK;
            const float2 f = __ldg(tab + idx);
            const float w = wx[ox] * wy[oy] * wz[oz];
            e0 = fmaf(w, f.x, e0);
            e1 = fmaf(w, f.y, e1);
        }
        enc[2 * l + 0] = e0;
        enc[2 * l + 1] = e1;
    }

    // MLP: h_j = relu(sum_k enc[k] * w1[j,k]); out = sigmoid(sum_j h_j * w2[j])
    float acc = 0.0f;
#pragma unroll 4
    for (int j = 0; j < 64; ++j) {
        const float4* __restrict__ wr = (const float4*)(s_w1 + j * 32);
        float h = 0.0f;
#pragma unroll
        for (int k = 0; k < 8; ++k) {
            const float4 wv = wr[k];
            h = fmaf(wv.x, enc[4 * k + 0], h);
            h = fmaf(wv.y, enc[4 * k + 1], h);
            h = fmaf(wv.z, enc[4 * k + 2], h);
            h = fmaf(wv.w, enc[4 * k + 3], h);
        }
        acc = fmaf(s_w2[j], fmaxf(h, 0.0f), acc);
    }

    out[i] = 1.0f / (1.0f + expf(-acc));
}

extern "C" void kernel_launch(void* const* d_in, const int* in_sizes, int n_in,
                              void* d_out, int out_size)
{
    const float*  pts   = (const float*)d_in[0];   // [NPTS, 3]
    const float2* table = (const float2*)d_in[1];  // [L, T, 2] -> float2[L*T]
    const float*  w1    = (const float*)d_in[2];   // [64, 32]
    const float*  w2    = (const float*)d_in[3];   // [64]
    float* out = (float*)d_out;

    ngp_fused_kernel<<<NPTS / 256, 256>>>(pts, table, w1, w2, out);
}